// round 6
// baseline (speedup 1.0000x reference)
#include <cuda_runtime.h>

// B=8, C=512, H=W=32 -> N=1024 tokens, 8 heads, d_k=64, inner=512
#define NB 8
#define NC 512
#define NN 1024
#define NH 8
#define DK 64

// Scratch (device globals; allocation-free rule)
static __device__ __align__(16) float g_q[(size_t)NB * NH * NN * DK];   // [B,H,N,64]
static __device__ __align__(16) float g_k[(size_t)NB * NH * NN * DK];
static __device__ __align__(16) float g_v[(size_t)NB * NH * NN * DK];
static __device__ __align__(16) float g_mid[(size_t)NB * NN * 512];     // [B,N,H*64]

// ---- tf32 helpers ---------------------------------------------------------
__device__ __forceinline__ unsigned f2tf(float f) {
    unsigned r; asm("cvt.rna.tf32.f32 %0, %1;" : "=r"(r) : "f"(f)); return r;
}
__device__ __forceinline__ uint4 cvt4(float4 v) {
    uint4 t; t.x = f2tf(v.x); t.y = f2tf(v.y); t.z = f2tf(v.z); t.w = f2tf(v.w);
    return t;
}
// D(16x8) += A(16x8) * B(8x8), tf32 in, fp32 accum.
__device__ __forceinline__ void mma8(float* d, const unsigned* a,
                                     unsigned b0, unsigned b1) {
    asm("mma.sync.aligned.m16n8k8.row.col.f32.tf32.tf32.f32 "
        "{%0,%1,%2,%3},{%4,%5,%6,%7},{%8,%9},{%0,%1,%2,%3};"
        : "+f"(d[0]), "+f"(d[1]), "+f"(d[2]), "+f"(d[3])
        : "r"(a[0]), "r"(a[1]), "r"(a[2]), "r"(a[3]), "r"(b0), "r"(b1));
}

// ---------------------------------------------------------------------------
// Kernel 1: fused transpose + QKV projection, tf32 mma.
// M = i (weight rows), N = n (tokens). Block 128i x 128n, 8 warps (2m x 4n),
// warp 64x32. k-tile 16, DOUBLE-BUFFERED smem, one sync per tile.
// ---------------------------------------------------------------------------
__global__ __launch_bounds__(256) void qkv_gemm(
    const float* __restrict__ x, const float* __restrict__ Wq,
    const float* __restrict__ bq, const float* __restrict__ Wkv,
    const float* __restrict__ bkv)
{
    __shared__ unsigned As[2][128][20];   // [i][c], stride%32==20 (cf-free frags)
    __shared__ unsigned Bs[2][16][136];   // [c][n], stride%32==8

    const int b = blockIdx.z, n0 = blockIdx.x * 128, i0 = blockIdx.y * 128;
    const float* W; const float* bias; int ir0;
    if (i0 < 512) { W = Wq;  bias = bq;  ir0 = i0; }
    else          { W = Wkv; bias = bkv; ir0 = i0 - 512; }

    const int tid = threadIdx.x, w = tid >> 5, lane = tid & 31;
    const int g = lane >> 2, tig = lane & 3;
    const int wm = w & 1, wn = w >> 1;
    const float* xb = x + (size_t)b * NC * NN;

    float acc[4][4][4];
#pragma unroll
    for (int am = 0; am < 4; am++) {
        float bv0 = bias[ir0 + wm * 64 + am * 16 + g];
        float bv1 = bias[ir0 + wm * 64 + am * 16 + 8 + g];
#pragma unroll
        for (int an = 0; an < 4; an++) {
            acc[am][an][0] = bv0; acc[am][an][1] = bv0;
            acc[am][an][2] = bv1; acc[am][an][3] = bv1;
        }
    }

    const int ar = tid >> 2, ac4 = tid & 3;    // A: rows ar, ar+64
    const int br = tid >> 5, bc4 = tid & 31;   // B: rows br, br+8

    float4 av[2], bv[2];
    // prologue: tile 0 -> regs -> buf0; tile 1 -> regs
#pragma unroll
    for (int u = 0; u < 2; u++) {
        av[u] = *(const float4*)(W + (size_t)(ir0 + ar + 64 * u) * NC + ac4 * 4);
        bv[u] = *(const float4*)(xb + (size_t)(br + 8 * u) * NN + n0 + bc4 * 4);
    }
#pragma unroll
    for (int u = 0; u < 2; u++) {
        *(uint4*)&As[0][ar + 64 * u][ac4 * 4] = cvt4(av[u]);
        *(uint4*)&Bs[0][br + 8 * u][bc4 * 4] = cvt4(bv[u]);
    }
#pragma unroll
    for (int u = 0; u < 2; u++) {
        av[u] = *(const float4*)(W + (size_t)(ir0 + ar + 64 * u) * NC + 16 + ac4 * 4);
        bv[u] = *(const float4*)(xb + (size_t)(16 + br + 8 * u) * NN + n0 + bc4 * 4);
    }
    __syncthreads();

#pragma unroll 1
    for (int t = 0; t < 32; t++) {
        const int p = t & 1;
        if (t < 31) {
#pragma unroll
            for (int u = 0; u < 2; u++) {
                *(uint4*)&As[1 - p][ar + 64 * u][ac4 * 4] = cvt4(av[u]);
                *(uint4*)&Bs[1 - p][br + 8 * u][bc4 * 4] = cvt4(bv[u]);
            }
        }
        if (t < 30) {
            const int c0 = (t + 2) * 16;
#pragma unroll
            for (int u = 0; u < 2; u++) {
                av[u] = *(const float4*)(W + (size_t)(ir0 + ar + 64 * u) * NC + c0 + ac4 * 4);
                bv[u] = *(const float4*)(xb + (size_t)(c0 + br + 8 * u) * NN + n0 + bc4 * 4);
            }
        }
        const unsigned (*Ap)[20] = As[p];
        const unsigned (*Bp)[136] = Bs[p];
#pragma unroll
        for (int ks = 0; ks < 2; ks++) {
            const int kb = ks * 8;
            unsigned a[4][4];
#pragma unroll
            for (int am = 0; am < 4; am++) {
                int mr = wm * 64 + am * 16;
                a[am][0] = Ap[mr + g][kb + tig];
                a[am][1] = Ap[mr + 8 + g][kb + tig];
                a[am][2] = Ap[mr + g][kb + tig + 4];
                a[am][3] = Ap[mr + 8 + g][kb + tig + 4];
            }
#pragma unroll
            for (int an = 0; an < 4; an++) {
                unsigned b0 = Bp[kb + tig][wn * 32 + an * 8 + g];
                unsigned b1 = Bp[kb + tig + 4][wn * 32 + an * 8 + g];
#pragma unroll
                for (int am = 0; am < 4; am++)
                    mma8(acc[am][an], a[am], b0, b1);
            }
        }
        __syncthreads();
    }

    float* dbase; int rel;
    if (i0 < 512)       { dbase = g_q; rel = i0; }
    else if (i0 < 1024) { dbase = g_k; rel = i0 - 512; }
    else                { dbase = g_v; rel = i0 - 1024; }
#pragma unroll
    for (int am = 0; am < 4; am++) {
        int ri = rel + wm * 64 + am * 16 + g;
        int hh = ri >> 6, dd = ri & 63;
        float* hb = dbase + (((size_t)b * NH + hh) * NN) * DK;
#pragma unroll
        for (int an = 0; an < 4; an++) {
            int n = n0 + wn * 32 + an * 8 + 2 * tig;
            hb[(size_t)n * DK + dd]           = acc[am][an][0];
            hb[(size_t)(n + 1) * DK + dd]     = acc[am][an][1];
            hb[(size_t)n * DK + dd + 8]       = acc[am][an][2];
            hb[(size_t)(n + 1) * DK + dd + 8] = acc[am][an][3];
        }
    }
}

// ---------------------------------------------------------------------------
// Kernel 2: attention, tf32 mma, flash-style online softmax.
// Block: 128 q rows, 4 warps x 32 q rows. 32-key tiles, d=64.
// DOUBLE-BUFFERED K/V smem; P relayout via intra-quad shuffles (no Ps smem).
// ---------------------------------------------------------------------------
__global__ __launch_bounds__(128) void attn_kernel()
{
    __shared__ unsigned Ks[2][32][68];    // [key][d]  stride%32==4
    __shared__ unsigned Vs[2][32][72];    // [key][d]  stride%32==8

    const int bh = blockIdx.y, q0 = blockIdx.x * 128;
    const int tid = threadIdx.x, w = tid >> 5, lane = tid & 31;
    const int g = lane >> 2, tig = lane & 3;
    const int qsel = tig & 1;
    const int src1 = (lane & ~3) | (tig >> 1);   // quad-lane holding col tig
    const int src2 = src1 + 2;                   // quad-lane holding col tig+4

    // Q fragments (A operand), pre-scaled by 1/8 (exact power of 2)
    const float* Qb = g_q + ((size_t)bh * NN + q0 + w * 32) * DK;
    unsigned qf[2][8][4];
#pragma unroll
    for (int am = 0; am < 2; am++)
#pragma unroll
        for (int s = 0; s < 8; s++) {
            qf[am][s][0] = f2tf(Qb[(size_t)(am * 16 + g) * DK + s * 8 + tig] * 0.125f);
            qf[am][s][1] = f2tf(Qb[(size_t)(am * 16 + 8 + g) * DK + s * 8 + tig] * 0.125f);
            qf[am][s][2] = f2tf(Qb[(size_t)(am * 16 + g) * DK + s * 8 + tig + 4] * 0.125f);
            qf[am][s][3] = f2tf(Qb[(size_t)(am * 16 + 8 + g) * DK + s * 8 + tig + 4] * 0.125f);
        }

    float o[2][8][4];
#pragma unroll
    for (int am = 0; am < 2; am++)
#pragma unroll
        for (int an = 0; an < 8; an++)
            o[am][an][0] = o[am][an][1] = o[am][an][2] = o[am][an][3] = 0.f;
    float m[2][2] = {{-1e30f, -1e30f}, {-1e30f, -1e30f}};
    float l[2][2] = {{0.f, 0.f}, {0.f, 0.f}};

    const float4* Kb4 = (const float4*)(g_k + (size_t)bh * NN * DK);
    const float4* Vb4 = (const float4*)(g_v + (size_t)bh * NN * DK);
    const int sr = tid >> 4, sc4 = tid & 15;

    float4 kr[4], vr[4];
    // prologue: tile0 -> buf0; tile1 -> regs
#pragma unroll
    for (int u = 0; u < 4; u++) { kr[u] = Kb4[tid + u * 128]; vr[u] = Vb4[tid + u * 128]; }
#pragma unroll
    for (int u = 0; u < 4; u++) {
        *(uint4*)&Ks[0][sr + 8 * u][sc4 * 4] = cvt4(kr[u]);
        *(uint4*)&Vs[0][sr + 8 * u][sc4 * 4] = cvt4(vr[u]);
    }
#pragma unroll
    for (int u = 0; u < 4; u++) { kr[u] = Kb4[512 + tid + u * 128]; vr[u] = Vb4[512 + tid + u * 128]; }
    __syncthreads();

#pragma unroll 1
    for (int jt = 0; jt < 32; jt++) {
        const int p = jt & 1;
        if (jt < 31) {
#pragma unroll
            for (int u = 0; u < 4; u++) {
                *(uint4*)&Ks[1 - p][sr + 8 * u][sc4 * 4] = cvt4(kr[u]);
                *(uint4*)&Vs[1 - p][sr + 8 * u][sc4 * 4] = cvt4(vr[u]);
            }
        }
        if (jt < 30) {
            const int base4 = (jt + 2) * 512;
#pragma unroll
            for (int u = 0; u < 4; u++) {
                kr[u] = Kb4[base4 + tid + u * 128];
                vr[u] = Vb4[base4 + tid + u * 128];
            }
        }
        const unsigned (*Kp)[68] = Ks[p];
        const unsigned (*Vp)[72] = Vs[p];

        // S = Q K^T
        float s[2][4][4];
#pragma unroll
        for (int am = 0; am < 2; am++)
#pragma unroll
            for (int an = 0; an < 4; an++)
                s[am][an][0] = s[am][an][1] = s[am][an][2] = s[am][an][3] = 0.f;
#pragma unroll
        for (int ks = 0; ks < 8; ks++)
#pragma unroll
            for (int an = 0; an < 4; an++) {
                unsigned b0 = Kp[an * 8 + g][ks * 8 + tig];
                unsigned b1 = Kp[an * 8 + g][ks * 8 + tig + 4];
                mma8(s[0][an], qf[0][ks], b0, b1);
                mma8(s[1][an], qf[1][ks], b0, b1);
            }

        // online softmax (per m-atom rows g, g+8); exps left in s[][][]
#pragma unroll
        for (int am = 0; am < 2; am++) {
            float tm0 = -1e30f, tm1 = -1e30f;
#pragma unroll
            for (int an = 0; an < 4; an++) {
                tm0 = fmaxf(tm0, fmaxf(s[am][an][0], s[am][an][1]));
                tm1 = fmaxf(tm1, fmaxf(s[am][an][2], s[am][an][3]));
            }
            tm0 = fmaxf(tm0, __shfl_xor_sync(0xffffffffu, tm0, 1));
            tm0 = fmaxf(tm0, __shfl_xor_sync(0xffffffffu, tm0, 2));
            tm1 = fmaxf(tm1, __shfl_xor_sync(0xffffffffu, tm1, 1));
            tm1 = fmaxf(tm1, __shfl_xor_sync(0xffffffffu, tm1, 2));
            float mn0 = fmaxf(m[am][0], tm0), mn1 = fmaxf(m[am][1], tm1);
            float corr0 = __expf(m[am][0] - mn0), corr1 = __expf(m[am][1] - mn1);
            m[am][0] = mn0; m[am][1] = mn1;

            float ps0 = 0.f, ps1 = 0.f;
#pragma unroll
            for (int an = 0; an < 4; an++) {
                s[am][an][0] = __expf(s[am][an][0] - mn0);
                s[am][an][1] = __expf(s[am][an][1] - mn0);
                s[am][an][2] = __expf(s[am][an][2] - mn1);
                s[am][an][3] = __expf(s[am][an][3] - mn1);
                ps0 += s[am][an][0] + s[am][an][1];
                ps1 += s[am][an][2] + s[am][an][3];
            }
            l[am][0] = l[am][0] * corr0 + ps0;
            l[am][1] = l[am][1] * corr1 + ps1;
#pragma unroll
            for (int an = 0; an < 8; an++) {
                o[am][an][0] *= corr0; o[am][an][1] *= corr0;
                o[am][an][2] *= corr1; o[am][an][3] *= corr1;
            }
        }

        // O += P V ; P D-frag -> A-frag via intra-quad shuffles.
        // Col c of a row lives in quad-lane c>>1, component c&1.
#pragma unroll
        for (int ks = 0; ks < 4; ks++) {
            unsigned pa[2][4];
#pragma unroll
            for (int am = 0; am < 2; am++) {
                float e0 = s[am][ks][0], e1 = s[am][ks][1];
                float e2 = s[am][ks][2], e3 = s[am][ks][3];
                float x0 = __shfl_sync(0xffffffffu, e0, src1);
                float y0 = __shfl_sync(0xffffffffu, e1, src1);
                float x1 = __shfl_sync(0xffffffffu, e2, src1);
                float y1 = __shfl_sync(0xffffffffu, e3, src1);
                float x2 = __shfl_sync(0xffffffffu, e0, src2);
                float y2 = __shfl_sync(0xffffffffu, e1, src2);
                float x3 = __shfl_sync(0xffffffffu, e2, src2);
                float y3 = __shfl_sync(0xffffffffu, e3, src2);
                pa[am][0] = f2tf(qsel ? y0 : x0);   // [g][ks*8+tig]
                pa[am][1] = f2tf(qsel ? y1 : x1);   // [g+8][ks*8+tig]
                pa[am][2] = f2tf(qsel ? y2 : x2);   // [g][ks*8+tig+4]
                pa[am][3] = f2tf(qsel ? y3 : x3);   // [g+8][ks*8+tig+4]
            }
#pragma unroll
            for (int an = 0; an < 8; an++) {
                unsigned b0 = Vp[ks * 8 + tig][an * 8 + g];
                unsigned b1 = Vp[ks * 8 + tig + 4][an * 8 + g];
                mma8(o[0][an], pa[0], b0, b1);
                mma8(o[1][an], pa[1], b0, b1);
            }
        }
        __syncthreads();
    }

#pragma unroll
    for (int am = 0; am < 2; am++) {
        l[am][0] += __shfl_xor_sync(0xffffffffu, l[am][0], 1);
        l[am][0] += __shfl_xor_sync(0xffffffffu, l[am][0], 2);
        l[am][1] += __shfl_xor_sync(0xffffffffu, l[am][1], 1);
        l[am][1] += __shfl_xor_sync(0xffffffffu, l[am][1], 2);
    }

    const int bb = bh >> 3, h = bh & 7;
    float* dst = g_mid + ((size_t)bb * NN + q0 + w * 32) * 512 + h * 64;
#pragma unroll
    for (int am = 0; am < 2; am++) {
        float inv0 = 1.f / l[am][0], inv1 = 1.f / l[am][1];
#pragma unroll
        for (int an = 0; an < 8; an++) {
            int dd = an * 8 + 2 * tig;
            *(float2*)(dst + (size_t)(am * 16 + g) * 512 + dd) =
                make_float2(o[am][an][0] * inv0, o[am][an][1] * inv0);
            *(float2*)(dst + (size_t)(am * 16 + 8 + g) * 512 + dd) =
                make_float2(o[am][an][2] * inv1, o[am][an][3] * inv1);
        }
    }
}

// ---------------------------------------------------------------------------
// Kernel 3: output projection, tf32 mma, double-buffered, k-tile 16.
// M = c (Wp rows), N = n: A = Wp[c][i], B = mid[n][i].
// ---------------------------------------------------------------------------
__global__ __launch_bounds__(256) void out_gemm(
    const float* __restrict__ Wp, const float* __restrict__ bp,
    float* __restrict__ out)
{
    __shared__ unsigned As[2][128][20];   // [c][i]
    __shared__ unsigned Bs[2][128][20];   // [n][i]

    const int b = blockIdx.z, n0 = blockIdx.x * 128, c0b = blockIdx.y * 128;
    const int tid = threadIdx.x, w = tid >> 5, lane = tid & 31;
    const int g = lane >> 2, tig = lane & 3;
    const int wm = w & 1, wn = w >> 1;
    const float* mb = g_mid + (size_t)b * NN * 512;

    float acc[4][4][4];
#pragma unroll
    for (int am = 0; am < 4; am++) {
        float bv0 = bp[c0b + wm * 64 + am * 16 + g];
        float bv1 = bp[c0b + wm * 64 + am * 16 + 8 + g];
#pragma unroll
        for (int an = 0; an < 4; an++) {
            acc[am][an][0] = bv0; acc[am][an][1] = bv0;
            acc[am][an][2] = bv1; acc[am][an][3] = bv1;
        }
    }

    const int ar = tid >> 2, ac4 = tid & 3;

    float4 av[2], bv[2];
#pragma unroll
    for (int u = 0; u < 2; u++) {
        av[u] = *(const float4*)(Wp + (size_t)(c0b + ar + 64 * u) * 512 + ac4 * 4);
        bv[u] = *(const float4*)(mb + (size_t)(n0 + ar + 64 * u) * 512 + ac4 * 4);
    }
#pragma unroll
    for (int u = 0; u < 2; u++) {
        *(uint4*)&As[0][ar + 64 * u][ac4 * 4] = cvt4(av[u]);
        *(uint4*)&Bs[0][ar + 64 * u][ac4 * 4] = cvt4(bv[u]);
    }
#pragma unroll
    for (int u = 0; u < 2; u++) {
        av[u] = *(const float4*)(Wp + (size_t)(c0b + ar + 64 * u) * 512 + 16 + ac4 * 4);
        bv[u] = *(const float4*)(mb + (size_t)(n0 + ar + 64 * u) * 512 + 16 + ac4 * 4);
    }
    __syncthreads();

#pragma unroll 1
    for (int t = 0; t < 32; t++) {
        const int p = t & 1;
        if (t < 31) {
#pragma unroll
            for (int u = 0; u < 2; u++) {
                *(uint4*)&As[1 - p][ar + 64 * u][ac4 * 4] = cvt4(av[u]);
                *(uint4*)&Bs[1 - p][ar + 64 * u][ac4 * 4] = cvt4(bv[u]);
            }
        }
        if (t < 30) {
            const int k0 = (t + 2) * 16;
#pragma unroll
            for (int u = 0; u < 2; u++) {
                av[u] = *(const float4*)(Wp + (size_t)(c0b + ar + 64 * u) * 512 + k0 + ac4 * 4);
                bv[u] = *(const float4*)(mb + (size_t)(n0 + ar + 64 * u) * 512 + k0 + ac4 * 4);
            }
        }
        const unsigned (*Ap)[20] = As[p];
        const unsigned (*Bp)[20] = Bs[p];
#pragma unroll
        for (int ks = 0; ks < 2; ks++) {
            const int kb = ks * 8;
            unsigned a[4][4];
#pragma unroll
            for (int am = 0; am < 4; am++) {
                int mr = wm * 64 + am * 16;
                a[am][0] = Ap[mr + g][kb + tig];
                a[am][1] = Ap[mr + 8 + g][kb + tig];
                a[am][2] = Ap[mr + g][kb + tig + 4];
                a[am][3] = Ap[mr + 8 + g][kb + tig + 4];
            }
#pragma unroll
            for (int an = 0; an < 4; an++) {
                unsigned b0 = Bp[wn * 32 + an * 8 + g][kb + tig];
                unsigned b1 = Bp[wn * 32 + an * 8 + g][kb + tig + 4];
#pragma unroll
                for (int am = 0; am < 4; am++)
                    mma8(acc[am][an], a[am], b0, b1);
            }
        }
        __syncthreads();
    }

#pragma unroll
    for (int am = 0; am < 4; am++) {
        int cc = c0b + wm * 64 + am * 16 + g;
#pragma unroll
        for (int an = 0; an < 4; an++) {
            int n = n0 + wn * 32 + an * 8 + 2 * tig;
            out[((size_t)b * NN + n) * 512 + cc]         = acc[am][an][0];
            out[((size_t)b * NN + n + 1) * 512 + cc]     = acc[am][an][1];
            out[((size_t)b * NN + n) * 512 + cc + 8]     = acc[am][an][2];
            out[((size_t)b * NN + n + 1) * 512 + cc + 8] = acc[am][an][3];
        }
    }
}

// ---------------------------------------------------------------------------
// Inputs: x, y, Wq, bq, Wkv, bkv, Wp, bp.  y unused. Output fp32 [B,N,C] flat.
// ---------------------------------------------------------------------------
extern "C" void kernel_launch(void* const* d_in, const int* in_sizes, int n_in,
                              void* d_out, int out_size)
{
    const float* x   = (const float*)d_in[0];
    const float* Wq  = (const float*)d_in[2];
    const float* bq  = (const float*)d_in[3];
    const float* Wkv = (const float*)d_in[4];
    const float* bkv = (const float*)d_in[5];
    const float* Wp  = (const float*)d_in[6];
    const float* bp  = (const float*)d_in[7];
    float* out = (float*)d_out;

    qkv_gemm<<<dim3(NN / 128, 1536 / 128, NB), 256>>>(x, Wq, bq, Wkv, bkv);
    attn_kernel<<<dim3(NN / 128, NB * NH), 128>>>();
    out_gemm<<<dim3(NN / 128, 512 / 128, NB), 256>>>(Wp, bp, out);
}

// round 7
// speedup vs baseline: 1.1246x; 1.1246x over previous
#include <cuda_runtime.h>

// B=8, C=512, H=W=32 -> N=1024 tokens, 8 heads, d_k=64, inner=512
#define NB 8
#define NC 512
#define NN 1024
#define NH 8
#define DK 64

// Scratch (device globals; allocation-free rule)
static __device__ __align__(16) float g_q[(size_t)NB * NH * NN * DK];   // [B,H,N,64] tf32-rounded
static __device__ __align__(16) float g_k[(size_t)NB * NH * NN * DK];
static __device__ __align__(16) float g_v[(size_t)NB * NH * NN * DK];
static __device__ __align__(16) float g_mid[(size_t)NB * NN * 512];     // [B,N,H*64] tf32-rounded
// tf32-pre-rounded copies of inputs
static __device__ __align__(16) float g_x2[(size_t)NB * NC * NN];
static __device__ __align__(16) float g_wq2[512 * 512];
static __device__ __align__(16) float g_wkv2[1024 * 512];
static __device__ __align__(16) float g_wp2[512 * 512];

// ---- helpers --------------------------------------------------------------
__device__ __forceinline__ unsigned f2tf(float f) {
    unsigned r; asm("cvt.rna.tf32.f32 %0, %1;" : "=r"(r) : "f"(f)); return r;
}
__device__ __forceinline__ uint4 cvt4(float4 v) {
    uint4 t; t.x = f2tf(v.x); t.y = f2tf(v.y); t.z = f2tf(v.z); t.w = f2tf(v.w);
    return t;
}
__device__ __forceinline__ void mma8(float* d, const unsigned* a,
                                     unsigned b0, unsigned b1) {
    asm("mma.sync.aligned.m16n8k8.row.col.f32.tf32.tf32.f32 "
        "{%0,%1,%2,%3},{%4,%5,%6,%7},{%8,%9},{%0,%1,%2,%3};"
        : "+f"(d[0]), "+f"(d[1]), "+f"(d[2]), "+f"(d[3])
        : "r"(a[0]), "r"(a[1]), "r"(a[2]), "r"(a[3]), "r"(b0), "r"(b1));
}
__device__ __forceinline__ unsigned sptr(const void* p) {
    return (unsigned)__cvta_generic_to_shared(p);
}
__device__ __forceinline__ void cp16(unsigned s, const void* g) {
    asm volatile("cp.async.cg.shared.global [%0], [%1], 16;" :: "r"(s), "l"(g));
}
__device__ __forceinline__ void cp_commit() {
    asm volatile("cp.async.commit_group;");
}
template <int N> __device__ __forceinline__ void cp_wait() {
    asm volatile("cp.async.wait_group %0;" :: "n"(N));
}

// ---------------------------------------------------------------------------
// Kernel 0: round inputs to tf32 once (values stay fp32-encoded).
// ---------------------------------------------------------------------------
#define X4N   1048576   // 8*512*1024/4
#define WQ4N  65536
#define WKV4N 131072
#define WP4N  65536
__global__ __launch_bounds__(256) void prep_round(
    const float4* __restrict__ x, const float4* __restrict__ wq,
    const float4* __restrict__ wkv, const float4* __restrict__ wp)
{
    int i = blockIdx.x * 256 + threadIdx.x;
    float4 v; uint4* dst;
    if (i < X4N)                    { v = x[i];   dst = (uint4*)g_x2 + i; }
    else if (i < X4N + WQ4N)        { int j = i - X4N; v = wq[j]; dst = (uint4*)g_wq2 + j; }
    else if (i < X4N + WQ4N + WKV4N){ int j = i - X4N - WQ4N; v = wkv[j]; dst = (uint4*)g_wkv2 + j; }
    else                            { int j = i - X4N - WQ4N - WKV4N; v = wp[j]; dst = (uint4*)g_wp2 + j; }
    *dst = cvt4(v);
}

// ---------------------------------------------------------------------------
// Kernel 1: fused transpose + QKV projection. tf32 mma, cp.async 3-stage.
// M = i (weight rows), N = n. Block 128i x 128n, 8 warps (2m x 4n), warp
// 64x32, k-tile 32. Epilogue rounds q/k/v to tf32.
// ---------------------------------------------------------------------------
#define QS 8960   // words per stage: A 128*36 + B 32*136
__global__ __launch_bounds__(256) void qkv_gemm(
    const float* __restrict__ bq, const float* __restrict__ bkv)
{
    extern __shared__ unsigned smq[];

    const int b = blockIdx.z, n0 = blockIdx.x * 128, i0 = blockIdx.y * 128;
    const float* W; const float* bias; int ir0;
    if (i0 < 512) { W = g_wq2;  bias = bq;  ir0 = i0; }
    else          { W = g_wkv2; bias = bkv; ir0 = i0 - 512; }

    const int tid = threadIdx.x, w = tid >> 5, lane = tid & 31;
    const int g = lane >> 2, tig = lane & 3;
    const int wm = w & 1, wn = w >> 1;
    const float* xb = g_x2 + (size_t)b * NC * NN;

    float acc[4][4][4];
#pragma unroll
    for (int am = 0; am < 4; am++) {
        float bv0 = bias[ir0 + wm * 64 + am * 16 + g];
        float bv1 = bias[ir0 + wm * 64 + am * 16 + 8 + g];
#pragma unroll
        for (int an = 0; an < 4; an++) {
            acc[am][an][0] = bv0; acc[am][an][1] = bv0;
            acc[am][an][2] = bv1; acc[am][an][3] = bv1;
        }
    }

    auto issue_tile = [&](int t) {
        if (t < 16) {
            unsigned* As = smq + (t % 3) * QS;
            unsigned* Bs = As + 4608;
            const int c0 = t * 32;
#pragma unroll
            for (int u = 0; u < 4; u++) {
                int idx = tid + u * 256, r = idx >> 3, c4 = idx & 7;
                cp16(sptr(As + r * 36 + c4 * 4),
                     W + (size_t)(ir0 + r) * NC + c0 + c4 * 4);
            }
#pragma unroll
            for (int u = 0; u < 4; u++) {
                int idx = tid + u * 256, r = idx >> 5, c4 = idx & 31;
                cp16(sptr(Bs + r * 136 + c4 * 4),
                     xb + (size_t)(c0 + r) * NN + n0 + c4 * 4);
            }
        }
        cp_commit();
    };

    issue_tile(0);
    issue_tile(1);

#pragma unroll 1
    for (int t = 0; t < 16; t++) {
        cp_wait<1>();
        __syncthreads();
        issue_tile(t + 2);
        const unsigned* As = smq + (t % 3) * QS;
        const unsigned* Bs = As + 4608;
#pragma unroll
        for (int ks = 0; ks < 4; ks++) {
            const int kb = ks * 8;
            unsigned a[4][4];
#pragma unroll
            for (int am = 0; am < 4; am++) {
                int mr = wm * 64 + am * 16;
                a[am][0] = As[(mr + g) * 36 + kb + tig];
                a[am][1] = As[(mr + 8 + g) * 36 + kb + tig];
                a[am][2] = As[(mr + g) * 36 + kb + tig + 4];
                a[am][3] = As[(mr + 8 + g) * 36 + kb + tig + 4];
            }
#pragma unroll
            for (int an = 0; an < 4; an++) {
                unsigned b0 = Bs[(kb + tig) * 136 + wn * 32 + an * 8 + g];
                unsigned b1 = Bs[(kb + tig + 4) * 136 + wn * 32 + an * 8 + g];
#pragma unroll
                for (int am = 0; am < 4; am++)
                    mma8(acc[am][an], a[am], b0, b1);
            }
        }
    }

    float* dbase; int rel;
    if (i0 < 512)       { dbase = g_q; rel = i0; }
    else if (i0 < 1024) { dbase = g_k; rel = i0 - 512; }
    else                { dbase = g_v; rel = i0 - 1024; }
#pragma unroll
    for (int am = 0; am < 4; am++) {
        int ri = rel + wm * 64 + am * 16 + g;
        int hh = ri >> 6, dd = ri & 63;
        float* hb = dbase + (((size_t)b * NH + hh) * NN) * DK;
#pragma unroll
        for (int an = 0; an < 4; an++) {
            int n = n0 + wn * 32 + an * 8 + 2 * tig;
            hb[(size_t)n * DK + dd]           = __uint_as_float(f2tf(acc[am][an][0]));
            hb[(size_t)(n + 1) * DK + dd]     = __uint_as_float(f2tf(acc[am][an][1]));
            hb[(size_t)n * DK + dd + 8]       = __uint_as_float(f2tf(acc[am][an][2]));
            hb[(size_t)(n + 1) * DK + dd + 8] = __uint_as_float(f2tf(acc[am][an][3]));
        }
    }
}

// ---------------------------------------------------------------------------
// Kernel 2: attention, tf32 mma, flash-style online softmax, cp.async 3-stage.
// Block: 128 q rows, 4 warps x 32 q rows, 32-key tiles, d=64.
// K/V raw bits (already tf32). P relayout via intra-quad shuffles.
// Epilogue rounds mid to tf32.
// ---------------------------------------------------------------------------
#define ATS 4480   // words per stage: Ks 32*68 + Vs 32*72
__global__ __launch_bounds__(128) void attn_kernel()
{
    extern __shared__ unsigned sma[];

    const int bh = blockIdx.y, q0 = blockIdx.x * 128;
    const int tid = threadIdx.x, w = tid >> 5, lane = tid & 31;
    const int g = lane >> 2, tig = lane & 3;
    const int qsel = tig & 1;
    const int src1 = (lane & ~3) | (tig >> 1);
    const int src2 = src1 + 2;

    // Q fragments: already tf32-rounded; *0.125f (power of 2) stays tf32-exact.
    const float* Qb = g_q + ((size_t)bh * NN + q0 + w * 32) * DK;
    unsigned qf[2][8][4];
#pragma unroll
    for (int am = 0; am < 2; am++)
#pragma unroll
        for (int s = 0; s < 8; s++) {
            qf[am][s][0] = __float_as_uint(Qb[(size_t)(am * 16 + g) * DK + s * 8 + tig] * 0.125f);
            qf[am][s][1] = __float_as_uint(Qb[(size_t)(am * 16 + 8 + g) * DK + s * 8 + tig] * 0.125f);
            qf[am][s][2] = __float_as_uint(Qb[(size_t)(am * 16 + g) * DK + s * 8 + tig + 4] * 0.125f);
            qf[am][s][3] = __float_as_uint(Qb[(size_t)(am * 16 + 8 + g) * DK + s * 8 + tig + 4] * 0.125f);
        }

    float o[2][8][4];
#pragma unroll
    for (int am = 0; am < 2; am++)
#pragma unroll
        for (int an = 0; an < 8; an++)
            o[am][an][0] = o[am][an][1] = o[am][an][2] = o[am][an][3] = 0.f;
    float m[2][2] = {{-1e30f, -1e30f}, {-1e30f, -1e30f}};
    float l[2][2] = {{0.f, 0.f}, {0.f, 0.f}};

    const float* Kb = g_k + (size_t)bh * NN * DK;
    const float* Vb = g_v + (size_t)bh * NN * DK;

    auto issue_tile = [&](int t) {
        if (t < 32) {
            unsigned* Ks = sma + (t % 3) * ATS;
            unsigned* Vs = Ks + 2176;
#pragma unroll
            for (int u = 0; u < 4; u++) {
                int idx = tid + u * 128, r = idx >> 4, c4 = idx & 15;
                cp16(sptr(Ks + r * 68 + c4 * 4), Kb + (size_t)(t * 32 + r) * DK + c4 * 4);
                cp16(sptr(Vs + r * 72 + c4 * 4), Vb + (size_t)(t * 32 + r) * DK + c4 * 4);
            }
        }
        cp_commit();
    };

    issue_tile(0);
    issue_tile(1);

#pragma unroll 1
    for (int jt = 0; jt < 32; jt++) {
        cp_wait<1>();
        __syncthreads();
        issue_tile(jt + 2);
        const unsigned* Kp = sma + (jt % 3) * ATS;
        const unsigned* Vp = Kp + 2176;

        // S = Q K^T
        float s[2][4][4];
#pragma unroll
        for (int am = 0; am < 2; am++)
#pragma unroll
            for (int an = 0; an < 4; an++)
                s[am][an][0] = s[am][an][1] = s[am][an][2] = s[am][an][3] = 0.f;
#pragma unroll
        for (int ks = 0; ks < 8; ks++)
#pragma unroll
            for (int an = 0; an < 4; an++) {
                unsigned b0 = Kp[(an * 8 + g) * 68 + ks * 8 + tig];
                unsigned b1 = Kp[(an * 8 + g) * 68 + ks * 8 + tig + 4];
                mma8(s[0][an], qf[0][ks], b0, b1);
                mma8(s[1][an], qf[1][ks], b0, b1);
            }

        // online softmax (per m-atom rows g, g+8); exps left in s[][][]
#pragma unroll
        for (int am = 0; am < 2; am++) {
            float tm0 = -1e30f, tm1 = -1e30f;
#pragma unroll
            for (int an = 0; an < 4; an++) {
                tm0 = fmaxf(tm0, fmaxf(s[am][an][0], s[am][an][1]));
                tm1 = fmaxf(tm1, fmaxf(s[am][an][2], s[am][an][3]));
            }
            tm0 = fmaxf(tm0, __shfl_xor_sync(0xffffffffu, tm0, 1));
            tm0 = fmaxf(tm0, __shfl_xor_sync(0xffffffffu, tm0, 2));
            tm1 = fmaxf(tm1, __shfl_xor_sync(0xffffffffu, tm1, 1));
            tm1 = fmaxf(tm1, __shfl_xor_sync(0xffffffffu, tm1, 2));
            float mn0 = fmaxf(m[am][0], tm0), mn1 = fmaxf(m[am][1], tm1);
            float corr0 = __expf(m[am][0] - mn0), corr1 = __expf(m[am][1] - mn1);
            m[am][0] = mn0; m[am][1] = mn1;

            float ps0 = 0.f, ps1 = 0.f;
#pragma unroll
            for (int an = 0; an < 4; an++) {
                s[am][an][0] = __expf(s[am][an][0] - mn0);
                s[am][an][1] = __expf(s[am][an][1] - mn0);
                s[am][an][2] = __expf(s[am][an][2] - mn1);
                s[am][an][3] = __expf(s[am][an][3] - mn1);
                ps0 += s[am][an][0] + s[am][an][1];
                ps1 += s[am][an][2] + s[am][an][3];
            }
            l[am][0] = l[am][0] * corr0 + ps0;
            l[am][1] = l[am][1] * corr1 + ps1;
#pragma unroll
            for (int an = 0; an < 8; an++) {
                o[am][an][0] *= corr0; o[am][an][1] *= corr0;
                o[am][an][2] *= corr1; o[am][an][3] *= corr1;
            }
        }

        // O += P V ; P D-frag -> A-frag via intra-quad shuffles.
#pragma unroll
        for (int ks = 0; ks < 4; ks++) {
            unsigned pa[2][4];
#pragma unroll
            for (int am = 0; am < 2; am++) {
                float e0 = s[am][ks][0], e1 = s[am][ks][1];
                float e2 = s[am][ks][2], e3 = s[am][ks][3];
                float x0 = __shfl_sync(0xffffffffu, e0, src1);
                float y0 = __shfl_sync(0xffffffffu, e1, src1);
                float x1 = __shfl_sync(0xffffffffu, e2, src1);
                float y1 = __shfl_sync(0xffffffffu, e3, src1);
                float x2 = __shfl_sync(0xffffffffu, e0, src2);
                float y2 = __shfl_sync(0xffffffffu, e1, src2);
                float x3 = __shfl_sync(0xffffffffu, e2, src2);
                float y3 = __shfl_sync(0xffffffffu, e3, src2);
                pa[am][0] = f2tf(qsel ? y0 : x0);
                pa[am][1] = f2tf(qsel ? y1 : x1);
                pa[am][2] = f2tf(qsel ? y2 : x2);
                pa[am][3] = f2tf(qsel ? y3 : x3);
            }
#pragma unroll
            for (int an = 0; an < 8; an++) {
                unsigned b0 = Vp[(ks * 8 + tig) * 72 + an * 8 + g];
                unsigned b1 = Vp[(ks * 8 + tig + 4) * 72 + an * 8 + g];
                mma8(o[0][an], pa[0], b0, b1);
                mma8(o[1][an], pa[1], b0, b1);
            }
        }
    }

#pragma unroll
    for (int am = 0; am < 2; am++) {
        l[am][0] += __shfl_xor_sync(0xffffffffu, l[am][0], 1);
        l[am][0] += __shfl_xor_sync(0xffffffffu, l[am][0], 2);
        l[am][1] += __shfl_xor_sync(0xffffffffu, l[am][1], 1);
        l[am][1] += __shfl_xor_sync(0xffffffffu, l[am][1], 2);
    }

    const int bb = bh >> 3, h = bh & 7;
    float* dst = g_mid + ((size_t)bb * NN + q0 + w * 32) * 512 + h * 64;
#pragma unroll
    for (int am = 0; am < 2; am++) {
        float inv0 = 1.f / l[am][0], inv1 = 1.f / l[am][1];
#pragma unroll
        for (int an = 0; an < 8; an++) {
            int dd = an * 8 + 2 * tig;
            dst[(size_t)(am * 16 + g) * 512 + dd]         = __uint_as_float(f2tf(o[am][an][0] * inv0));
            dst[(size_t)(am * 16 + g) * 512 + dd + 1]     = __uint_as_float(f2tf(o[am][an][1] * inv0));
            dst[(size_t)(am * 16 + 8 + g) * 512 + dd]     = __uint_as_float(f2tf(o[am][an][2] * inv1));
            dst[(size_t)(am * 16 + 8 + g) * 512 + dd + 1] = __uint_as_float(f2tf(o[am][an][3] * inv1));
        }
    }
}

// ---------------------------------------------------------------------------
// Kernel 3: output projection, tf32 mma, cp.async 3-stage, k-tile 32.
// M = c (Wp rows), N = n: A = Wp2[c][i], B = mid[n][i] (both pre-rounded).
// ---------------------------------------------------------------------------
#define OS 9216   // words per stage: A 128*36 + B 128*36
__global__ __launch_bounds__(256) void out_gemm(
    const float* __restrict__ bp, float* __restrict__ out)
{
    extern __shared__ unsigned smo[];

    const int b = blockIdx.z, n0 = blockIdx.x * 128, c0b = blockIdx.y * 128;
    const int tid = threadIdx.x, w = tid >> 5, lane = tid & 31;
    const int g = lane >> 2, tig = lane & 3;
    const int wm = w & 1, wn = w >> 1;
    const float* mb = g_mid + (size_t)b * NN * 512;

    float acc[4][4][4];
#pragma unroll
    for (int am = 0; am < 4; am++) {
        float bv0 = bp[c0b + wm * 64 + am * 16 + g];
        float bv1 = bp[c0b + wm * 64 + am * 16 + 8 + g];
#pragma unroll
        for (int an = 0; an < 4; an++) {
            acc[am][an][0] = bv0; acc[am][an][1] = bv0;
            acc[am][an][2] = bv1; acc[am][an][3] = bv1;
        }
    }

    auto issue_tile = [&](int t) {
        if (t < 16) {
            unsigned* As = smo + (t % 3) * OS;
            unsigned* Bs = As + 4608;
            const int k0 = t * 32;
#pragma unroll
            for (int u = 0; u < 4; u++) {
                int idx = tid + u * 256, r = idx >> 3, c4 = idx & 7;
                cp16(sptr(As + r * 36 + c4 * 4),
                     g_wp2 + (size_t)(c0b + r) * 512 + k0 + c4 * 4);
                cp16(sptr(Bs + r * 36 + c4 * 4),
                     mb + (size_t)(n0 + r) * 512 + k0 + c4 * 4);
            }
        }
        cp_commit();
    };

    issue_tile(0);
    issue_tile(1);

#pragma unroll 1
    for (int t = 0; t < 16; t++) {
        cp_wait<1>();
        __syncthreads();
        issue_tile(t + 2);
        const unsigned* As = smo + (t % 3) * OS;
        const unsigned* Bs = As + 4608;
#pragma unroll
        for (int ks = 0; ks < 4; ks++) {
            const int kb = ks * 8;
            unsigned a[4][4];
#pragma unroll
            for (int am = 0; am < 4; am++) {
                int mr = wm * 64 + am * 16;
                a[am][0] = As[(mr + g) * 36 + kb + tig];
                a[am][1] = As[(mr + 8 + g) * 36 + kb + tig];
                a[am][2] = As[(mr + g) * 36 + kb + tig + 4];
                a[am][3] = As[(mr + 8 + g) * 36 + kb + tig + 4];
            }
#pragma unroll
            for (int an = 0; an < 4; an++) {
                unsigned b0 = Bs[(wn * 32 + an * 8 + g) * 36 + kb + tig];
                unsigned b1 = Bs[(wn * 32 + an * 8 + g) * 36 + kb + tig + 4];
#pragma unroll
                for (int am = 0; am < 4; am++)
                    mma8(acc[am][an], a[am], b0, b1);
            }
        }
    }

#pragma unroll
    for (int am = 0; am < 4; am++) {
        int cc = c0b + wm * 64 + am * 16 + g;
#pragma unroll
        for (int an = 0; an < 4; an++) {
            int n = n0 + wn * 32 + an * 8 + 2 * tig;
            out[((size_t)b * NN + n) * 512 + cc]         = acc[am][an][0];
            out[((size_t)b * NN + n + 1) * 512 + cc]     = acc[am][an][1];
            out[((size_t)b * NN + n) * 512 + cc + 8]     = acc[am][an][2];
            out[((size_t)b * NN + n + 1) * 512 + cc + 8] = acc[am][an][3];
        }
    }
}

// ---------------------------------------------------------------------------
// Inputs: x, y, Wq, bq, Wkv, bkv, Wp, bp.  y unused. Output fp32 [B,N,C] flat.
// ---------------------------------------------------------------------------
extern "C" void kernel_launch(void* const* d_in, const int* in_sizes, int n_in,
                              void* d_out, int out_size)
{
    const float* x   = (const float*)d_in[0];
    const float* Wq  = (const float*)d_in[2];
    const float* bq  = (const float*)d_in[3];
    const float* Wkv = (const float*)d_in[4];
    const float* bkv = (const float*)d_in[5];
    const float* Wp  = (const float*)d_in[6];
    const float* bp  = (const float*)d_in[7];
    float* out = (float*)d_out;

    cudaFuncSetAttribute(qkv_gemm, cudaFuncAttributeMaxDynamicSharedMemorySize, 3 * QS * 4);
    cudaFuncSetAttribute(attn_kernel, cudaFuncAttributeMaxDynamicSharedMemorySize, 3 * ATS * 4);
    cudaFuncSetAttribute(out_gemm, cudaFuncAttributeMaxDynamicSharedMemorySize, 3 * OS * 4);

    prep_round<<<5120, 256>>>((const float4*)x, (const float4*)Wq,
                              (const float4*)Wkv, (const float4*)Wp);
    qkv_gemm<<<dim3(NN / 128, 1536 / 128, NB), 256, 3 * QS * 4>>>(bq, bkv);
    attn_kernel<<<dim3(NN / 128, NB * NH), 128, 3 * ATS * 4>>>();
    out_gemm<<<dim3(NN / 128, 512 / 128, NB), 256, 3 * OS * 4>>>(bp, out);
}